// round 14
// baseline (speedup 1.0000x reference)
#include <cuda_runtime.h>
#include <cuda_bf16.h>
#include <math.h>

#define N 4096
#define D 1024
#define NCLS 128
#define TM 128
#define TN 128
#define NCHUNK 8             // 8 chunks of 128 fp8 k-elements
#define NJT (N / TN)         // 32
#define NTILES (NJT * (NJT + 1) / 2)  // 528 upper-tri tiles
#define STAGES 3
#define STAGE_BYTES 32768    // A 16KB + B 16KB (128 rows x 128 B each)
#define B_OFF 16384

// dynamic smem layout
#define SM_LABS   64                    // int[128]
#define SM_FP     576                   // int[128]
#define SM_ROWRED 1088                  // float[2*128]
#define SM_COLRED 2112                  // float[4*128]
#define SM_TILES  4160
#define SMEM_DYN  (SM_TILES + 1024 + STAGES * STAGE_BYTES)  // 103488

// -------- device scratch --------
__device__ __align__(16) unsigned char g_xq[(size_t)N * D];  // e4m3(16 * xhat), 4 MB
__device__ int   g_lab[N];
__device__ int   g_first[NCLS];
__device__ int   g_second[NCLS];
__device__ int   g_hist[NCLS];
__device__ float g_posval[N];
__device__ float g_partial[NJT * N];
__device__ int   g_is64;

#define SWZ(x) ((unsigned)(x) ^ ((((unsigned)(x)) >> 3) & 0x70u))

__device__ __forceinline__ unsigned smem_u32(const void* p) {
    unsigned a;
    asm("{ .reg .u64 t; cvta.to.shared.u64 t, %1; cvt.u32.u64 %0, t; }" : "=r"(a) : "l"(p));
    return a;
}
__device__ __forceinline__ void ldsm4(unsigned r[4], unsigned addr) {
    asm volatile("ldmatrix.sync.aligned.m8n8.x4.shared.b16 {%0,%1,%2,%3}, [%4];"
                 : "=r"(r[0]), "=r"(r[1]), "=r"(r[2]), "=r"(r[3]) : "r"(addr));
}
// fp8 e4m3 MMA, k32: byte-layout of fragments identical to bf16 k16
__device__ __forceinline__ void mma16832(float d[4], const unsigned a[4], unsigned b0, unsigned b1) {
    asm volatile(
        "mma.sync.aligned.m16n8k32.row.col.f32.e4m3.e4m3.f32 "
        "{%0,%1,%2,%3}, {%4,%5,%6,%7}, {%8,%9}, {%0,%1,%2,%3};"
        : "+f"(d[0]), "+f"(d[1]), "+f"(d[2]), "+f"(d[3])
        : "r"(a[0]), "r"(a[1]), "r"(a[2]), "r"(a[3]), "r"(b0), "r"(b1));
}
__device__ __forceinline__ void cpasync16(unsigned dst, const void* src) {
    asm volatile("cp.async.cg.shared.global [%0], [%1], 16;" :: "r"(dst), "l"(src));
}

// -------- kernel 1: init + detect y_true width --------
__global__ void k_init(const int* __restrict__ Y32) {
    int t = threadIdx.x;
    int any = 0;
    for (int i = 2 * t + 1; i < N; i += 2 * blockDim.x) any |= Y32[i];
    int any_blk = __syncthreads_or(any);
    if (t == 0) g_is64 = (any_blk == 0) ? 1 : 0;
    if (t < NCLS) {
        g_hist[t] = 0;
        g_first[t] = 0x7fffffff;
        g_second[t] = 0x7fffffff;
    }
    for (int i = t; i < N; i += blockDim.x) g_posval[i] = 0.0f;
}

// -------- kernel 2: normalize rows -> fp8(16*xhat), labels, histogram, first[c] --------
__global__ __launch_bounds__(256) void k_prep(const float* __restrict__ X,
                                              const void* __restrict__ Yv) {
    int i = blockIdx.x;
    int t = threadIdx.x;
    float4 v = ((const float4*)(X + (size_t)i * D))[t];
    float s = v.x * v.x + v.y * v.y + v.z * v.z + v.w * v.w;
#pragma unroll
    for (int o = 16; o; o >>= 1) s += __shfl_down_sync(0xffffffffu, s, o);
    __shared__ float ws[8];
    if ((t & 31) == 0) ws[t >> 5] = s;
    __syncthreads();
    if (t == 0) {
        float tot = 0.0f;
#pragma unroll
        for (int j = 0; j < 8; ++j) tot += ws[j];
        ws[0] = 16.0f / fmaxf(sqrtf(tot), 1e-8f);   // scale by 16 for e4m3 range
        int lab = g_is64 ? (int)((const long long*)Yv)[i] : ((const int*)Yv)[i];
        lab = max(0, min(lab, NCLS - 1));
        g_lab[i] = lab;
        atomicAdd(&g_hist[lab], 1);
        atomicMin(&g_first[lab], i);
    }
    __syncthreads();
    float inv = ws[0];
    unsigned short r0, r1;
    asm("cvt.rn.satfinite.e4m3x2.f32 %0, %1, %2;" : "=h"(r0) : "f"(v.y * inv), "f"(v.x * inv));
    asm("cvt.rn.satfinite.e4m3x2.f32 %0, %1, %2;" : "=h"(r1) : "f"(v.w * inv), "f"(v.z * inv));
    *(unsigned*)&g_xq[(size_t)i * D + (size_t)t * 4] = (unsigned)r0 | ((unsigned)r1 << 16);
}

// -------- kernel 3: per-class second-occurrence (O(N)) --------
__global__ __launch_bounds__(256) void k_fp2() {
    int i = blockIdx.x * 256 + threadIdx.x;
    if (i < N) {
        int c = g_lab[i];
        if (i != g_first[c]) atomicMin(&g_second[c], i);
    }
}

// -------- kernel 4: symmetric fp8 mma.sync GEMM + fused row/col masked-exp epilogue --------
// 1D grid of 528 upper-tri tiles (a <= b); 256 threads = 8 warps 4(m) x 2(n), warp 32x64.
__global__ __launch_bounds__(256, 2) void k_gemm() {
    extern __shared__ __align__(16) char sm[];
    const unsigned sbase = smem_u32(sm);
    const unsigned tb = (sbase + SM_TILES + 1023u) & ~1023u;
    const int tid = threadIdx.x;
    const int wid = tid >> 5, lane = tid & 31;
    const int wm = wid >> 1, wn = wid & 1;

    // decode upper-tri tile index t -> (a, b), a <= b
    const int t = blockIdx.x;
    int b = (int)((sqrtf(8.0f * (float)t + 1.0f) - 1.0f) * 0.5f);
    while (b * (b + 1) / 2 > t) --b;
    while ((b + 1) * (b + 2) / 2 <= t) ++b;
    const int a = t - b * (b + 1) / 2;
    const bool offdiag = (a != b);

    const int ibase = a * TM, jbase = b * TN;
    const int m0 = wm * 32, n0 = wn * 64;

    // j-block labels and first-pos into smem
    if (tid < TN) {
        int j = jbase + tid;
        int c = g_lab[j];
        ((int*)(sm + SM_LABS))[tid] = c;
        ((int*)(sm + SM_FP))[tid] = (j == g_first[c]) ? g_second[c] : g_first[c];
    }

    // loader mapping: each thread 16B, rows tid>>3 step 32, seg = tid&7
    const int lrow = tid >> 3, lseg = tid & 7;
    const char* gAb = (const char*)g_xq + (size_t)(ibase + lrow) * D + lseg * 16;
    const char* gBb = (const char*)g_xq + (size_t)(jbase + lrow) * D + lseg * 16;
    unsigned ldoff[4];
#pragma unroll
    for (int r = 0; r < 4; ++r) ldoff[r] = SWZ((lrow + r * 32) * 128 + lseg * 16);

#define LOAD_STAGE(c)                                                              \
    do {                                                                           \
        unsigned _st = tb + (unsigned)((c) % STAGES) * STAGE_BYTES;                \
        _Pragma("unroll")                                                          \
        for (int _r = 0; _r < 4; ++_r) {                                           \
            cpasync16(_st + ldoff[_r], gAb + (size_t)_r * 32 * D + (c) * 128);     \
            cpasync16(_st + B_OFF + ldoff[_r], gBb + (size_t)_r * 32 * D + (c) * 128); \
        }                                                                          \
    } while (0)

    LOAD_STAGE(0);
    asm volatile("cp.async.commit_group;" ::: "memory");
    LOAD_STAGE(1);
    asm volatile("cp.async.commit_group;" ::: "memory");

    float acc[2][8][4];
#pragma unroll
    for (int mi = 0; mi < 2; ++mi)
#pragma unroll
        for (int ni = 0; ni < 8; ++ni)
#pragma unroll
            for (int q = 0; q < 4; ++q) acc[mi][ni][q] = 0.0f;

    // precomputed ldsm row bases: addr = st + rowbase + (cb ^ sw)
    const int lm16 = lane & 15;
    const int khi = (lane >> 4) * 16;
    unsigned rbA0 = (unsigned)(m0 + lm16) * 128u;
    unsigned rbA1 = (unsigned)(m0 + 16 + lm16) * 128u;
    unsigned swA0 = (rbA0 >> 3) & 0x70u, swA1 = (rbA1 >> 3) & 0x70u;
    unsigned rbB[4], swB[4];
#pragma unroll
    for (int nt = 0; nt < 4; ++nt) {
        rbB[nt] = (unsigned)(n0 + nt * 16 + lm16) * 128u;
        swB[nt] = (rbB[nt] >> 3) & 0x70u;
    }

#pragma unroll 1
    for (int c = 0; c < NCHUNK; ++c) {
        if (c + 2 < NCHUNK) LOAD_STAGE(c + 2);
        asm volatile("cp.async.commit_group;" ::: "memory");
        asm volatile("cp.async.wait_group %0;" :: "n"(STAGES - 1) : "memory");
        __syncthreads();
        const unsigned st = tb + (unsigned)(c % STAGES) * STAGE_BYTES;
#pragma unroll
        for (int kk = 0; kk < 4; ++kk) {
            const unsigned cb = (unsigned)(kk * 32 + khi);
            unsigned a0[4], a1[4], bb[4][4];
            ldsm4(a0, st + rbA0 + (cb ^ swA0));
            ldsm4(a1, st + rbA1 + (cb ^ swA1));
#pragma unroll
            for (int nt = 0; nt < 4; ++nt)
                ldsm4(bb[nt], st + B_OFF + rbB[nt] + (cb ^ swB[nt]));
#pragma unroll
            for (int nt = 0; nt < 4; ++nt) {
                mma16832(acc[0][2 * nt + 0], a0, bb[nt][0], bb[nt][2]);
                mma16832(acc[0][2 * nt + 1], a0, bb[nt][1], bb[nt][3]);
                mma16832(acc[1][2 * nt + 0], a1, bb[nt][0], bb[nt][2]);
                mma16832(acc[1][2 * nt + 1], a1, bb[nt][1], bb[nt][3]);
            }
        }
        __syncthreads();
    }

    // ---- fused epilogue: row-sums (slot b) and, off-diagonal, col-sums (slot a) ----
    const int* labsB = (const int*)(sm + SM_LABS);
    const int* fpB = (const int*)(sm + SM_FP);

    int rowlab[4], rowfp[4];
#pragma unroll
    for (int mi = 0; mi < 2; ++mi)
#pragma unroll
        for (int h = 0; h < 2; ++h) {
            int grow = ibase + m0 + mi * 16 + h * 8 + (lane >> 2);
            int c = g_lab[grow];
            rowlab[mi * 2 + h] = c;
            rowfp[mi * 2 + h] = (grow == g_first[c]) ? g_second[c] : g_first[c];
        }

    float rs4[4] = {0.0f, 0.0f, 0.0f, 0.0f};
    float cs[8][2];
#pragma unroll
    for (int ni = 0; ni < 8; ++ni) { cs[ni][0] = 0.0f; cs[ni][1] = 0.0f; }

    const float SCL = 0.25f / 256.0f;  // acc = 256*cos -> S = 0.25*cos + 0.25
#pragma unroll
    for (int mi = 0; mi < 2; ++mi)
#pragma unroll
        for (int h = 0; h < 2; ++h) {
            const int ri = mi * 2 + h;
            const int rl = rowlab[ri], rf = rowfp[ri];
            const int grow = ibase + m0 + mi * 16 + h * 8 + (lane >> 2);
#pragma unroll
            for (int ni = 0; ni < 8; ++ni) {
                const int cl0 = n0 + ni * 8 + (lane & 3) * 2;
#pragma unroll
                for (int e = 0; e < 2; ++e) {
                    const int cl = cl0 + e;
                    float S = acc[mi][ni][h * 2 + e] * SCL + 0.25f;
                    float ex = __expf(S);
                    if (labsB[cl] != rl) { rs4[ri] += ex; cs[ni][e] += ex; }
                    if (jbase + cl == rf) g_posval[grow] = S;                 // unique writer
                    if (offdiag && fpB[cl] == grow) g_posval[jbase + cl] = S; // unique writer
                }
            }
        }

    // row reduce: lanes sharing lane>>2 hold the same rows
#pragma unroll
    for (int ri = 0; ri < 4; ++ri) {
        rs4[ri] += __shfl_xor_sync(0xffffffffu, rs4[ri], 1);
        rs4[ri] += __shfl_xor_sync(0xffffffffu, rs4[ri], 2);
    }
    float* rowred = (float*)(sm + SM_ROWRED);
    if ((lane & 3) == 0) {
#pragma unroll
        for (int mi = 0; mi < 2; ++mi)
#pragma unroll
            for (int h = 0; h < 2; ++h)
                rowred[wn * TM + m0 + mi * 16 + h * 8 + (lane >> 2)] = rs4[mi * 2 + h];
    }

    // col reduce: lanes sharing lane&3 hold the same cols
    if (offdiag) {
#pragma unroll
        for (int ni = 0; ni < 8; ++ni)
#pragma unroll
            for (int e = 0; e < 2; ++e) {
                cs[ni][e] += __shfl_xor_sync(0xffffffffu, cs[ni][e], 4);
                cs[ni][e] += __shfl_xor_sync(0xffffffffu, cs[ni][e], 8);
                cs[ni][e] += __shfl_xor_sync(0xffffffffu, cs[ni][e], 16);
            }
        float* colred = (float*)(sm + SM_COLRED);
        if (lane < 4) {
#pragma unroll
            for (int ni = 0; ni < 8; ++ni)
#pragma unroll
                for (int e = 0; e < 2; ++e)
                    colred[wm * TN + n0 + ni * 8 + lane * 2 + e] = cs[ni][e];
        }
    }
    __syncthreads();

    if (tid < TM)
        g_partial[b * N + ibase + tid] = rowred[tid] + rowred[TM + tid];
    if (offdiag && tid < TN) {
        const float* colred = (const float*)(sm + SM_COLRED);
        g_partial[a * N + jbase + tid] =
            colred[tid] + colred[TN + tid] + colred[2 * TN + tid] + colred[3 * TN + tid];
    }
}

// -------- kernel 5: combine partials, per-row loss, scalar mean --------
__global__ __launch_bounds__(1024) void k_final(float* __restrict__ out) {
    int t = threadIdx.x;
    float ls = 0.0f;
    for (int i = t; i < N; i += 1024) {
        float ns = 0.0f;
#pragma unroll
        for (int p = 0; p < NJT; ++p) ns += g_partial[p * N + i];
        float pv = g_posval[i];
        float Z = (float)(N - 2 + g_hist[g_lab[i]]);  // exp(0) structural zeros
        ls += __logf(__expf(pv) + ns + Z) - pv;
    }
#pragma unroll
    for (int o = 16; o; o >>= 1) ls += __shfl_down_sync(0xffffffffu, ls, o);
    __shared__ float ws[32];
    if ((t & 31) == 0) ws[t >> 5] = ls;
    __syncthreads();
    if (t == 0) {
        float tot = 0.0f;
#pragma unroll
        for (int j = 0; j < 32; ++j) tot += ws[j];
        out[0] = tot / (float)N;
    }
}

// -------- launch --------
extern "C" void kernel_launch(void* const* d_in, const int* in_sizes, int n_in,
                              void* d_out, int out_size) {
    const float* X = (const float*)d_in[0];
    const void* Y = d_in[1];
    float* out = (float*)d_out;

    static int smem_set = 0;
    if (!smem_set) {
        cudaFuncSetAttribute(k_gemm, cudaFuncAttributeMaxDynamicSharedMemorySize, SMEM_DYN);
        smem_set = 1;
    }

    k_init<<<1, 256>>>((const int*)Y);
    k_prep<<<N, 256>>>(X, Y);
    k_fp2<<<N / 256, 256>>>();
    k_gemm<<<NTILES, 256, SMEM_DYN>>>();
    k_final<<<1, 1024>>>(out);
}

// round 15
// speedup vs baseline: 1.0051x; 1.0051x over previous
#include <cuda_runtime.h>
#include <cuda_bf16.h>
#include <math.h>

#define N 4096
#define D 1024
#define NCLS 128
#define TM 128
#define TN 128
#define NCHUNK 8             // 8 chunks of 128 fp8 k-elements
#define NJT (N / TN)         // 32
#define NTILES (NJT * (NJT + 1) / 2)  // 528 upper-tri tiles
#define STAGES 3
#define STAGE_BYTES 32768    // A 16KB + B 16KB (128 rows x 128 B each)
#define B_OFF 16384

// dynamic smem layout
#define SM_LABS   64                    // int[128]
#define SM_FP     576                   // int[128]
#define SM_ROWRED 1088                  // float[2*128]
#define SM_COLRED 2112                  // float[4*128]
#define SM_TILES  4160
#define SMEM_DYN  (SM_TILES + 1024 + STAGES * STAGE_BYTES)  // 103488

// -------- device scratch --------
__device__ __align__(16) unsigned char g_xq[(size_t)N * D];  // e4m3(16 * xhat), 4 MB
__device__ int   g_lab[N];
__device__ int   g_first[NCLS];
__device__ int   g_second[NCLS];
__device__ int   g_hist[NCLS];
__device__ float g_posval[N];
__device__ float g_partial[NJT * N];
__device__ int   g_is64;

#define SWZ(x) ((unsigned)(x) ^ ((((unsigned)(x)) >> 3) & 0x70u))

__device__ __forceinline__ unsigned smem_u32(const void* p) {
    unsigned a;
    asm("{ .reg .u64 t; cvta.to.shared.u64 t, %1; cvt.u32.u64 %0, t; }" : "=r"(a) : "l"(p));
    return a;
}
__device__ __forceinline__ void ldsm4(unsigned r[4], unsigned addr) {
    asm volatile("ldmatrix.sync.aligned.m8n8.x4.shared.b16 {%0,%1,%2,%3}, [%4];"
                 : "=r"(r[0]), "=r"(r[1]), "=r"(r[2]), "=r"(r[3]) : "r"(addr));
}
// fp8 e4m3 MMA, k32: byte-layout of fragments identical to bf16 k16
__device__ __forceinline__ void mma16832(float d[4], const unsigned a[4], unsigned b0, unsigned b1) {
    asm volatile(
        "mma.sync.aligned.m16n8k32.row.col.f32.e4m3.e4m3.f32 "
        "{%0,%1,%2,%3}, {%4,%5,%6,%7}, {%8,%9}, {%0,%1,%2,%3};"
        : "+f"(d[0]), "+f"(d[1]), "+f"(d[2]), "+f"(d[3])
        : "r"(a[0]), "r"(a[1]), "r"(a[2]), "r"(a[3]), "r"(b0), "r"(b1));
}
__device__ __forceinline__ void cpasync16(unsigned dst, const void* src) {
    asm volatile("cp.async.cg.shared.global [%0], [%1], 16;" :: "r"(dst), "l"(src));
}

// -------- kernel 1: init + detect y_true width --------
__global__ void k_init(const int* __restrict__ Y32) {
    int t = threadIdx.x;
    int any = 0;
    for (int i = 2 * t + 1; i < N; i += 2 * blockDim.x) any |= Y32[i];
    int any_blk = __syncthreads_or(any);
    if (t == 0) g_is64 = (any_blk == 0) ? 1 : 0;
    if (t < NCLS) {
        g_hist[t] = 0;
        g_first[t] = 0x7fffffff;
        g_second[t] = 0x7fffffff;
    }
    for (int i = t; i < N; i += blockDim.x) g_posval[i] = 0.0f;
}

// -------- kernel 2: normalize rows -> fp8(16*xhat), labels, histogram, first[c] --------
__global__ __launch_bounds__(256) void k_prep(const float* __restrict__ X,
                                              const void* __restrict__ Yv) {
    int i = blockIdx.x;
    int t = threadIdx.x;
    float4 v = ((const float4*)(X + (size_t)i * D))[t];
    float s = v.x * v.x + v.y * v.y + v.z * v.z + v.w * v.w;
#pragma unroll
    for (int o = 16; o; o >>= 1) s += __shfl_down_sync(0xffffffffu, s, o);
    __shared__ float ws[8];
    if ((t & 31) == 0) ws[t >> 5] = s;
    __syncthreads();
    if (t == 0) {
        float tot = 0.0f;
#pragma unroll
        for (int j = 0; j < 8; ++j) tot += ws[j];
        ws[0] = 16.0f / fmaxf(sqrtf(tot), 1e-8f);   // scale by 16 for e4m3 range
        int lab = g_is64 ? (int)((const long long*)Yv)[i] : ((const int*)Yv)[i];
        lab = max(0, min(lab, NCLS - 1));
        g_lab[i] = lab;
        atomicAdd(&g_hist[lab], 1);
        atomicMin(&g_first[lab], i);
    }
    __syncthreads();
    float inv = ws[0];
    unsigned short r0, r1;
    asm("cvt.rn.satfinite.e4m3x2.f32 %0, %1, %2;" : "=h"(r0) : "f"(v.y * inv), "f"(v.x * inv));
    asm("cvt.rn.satfinite.e4m3x2.f32 %0, %1, %2;" : "=h"(r1) : "f"(v.w * inv), "f"(v.z * inv));
    *(unsigned*)&g_xq[(size_t)i * D + (size_t)t * 4] = (unsigned)r0 | ((unsigned)r1 << 16);
}

// -------- kernel 3: per-class second-occurrence (O(N)) --------
__global__ __launch_bounds__(256) void k_fp2() {
    int i = blockIdx.x * 256 + threadIdx.x;
    if (i < N) {
        int c = g_lab[i];
        if (i != g_first[c]) atomicMin(&g_second[c], i);
    }
}

// -------- kernel 4: symmetric fp8 mma.sync GEMM + fused row/col masked-exp epilogue --------
// 1D grid of 528 upper-tri tiles (a <= b); 256 threads = 8 warps 4(m) x 2(n), warp 32x64.
__global__ __launch_bounds__(256, 2) void k_gemm() {
    extern __shared__ __align__(16) char sm[];
    const unsigned sbase = smem_u32(sm);
    const unsigned tb = (sbase + SM_TILES + 1023u) & ~1023u;
    const int tid = threadIdx.x;
    const int wid = tid >> 5, lane = tid & 31;
    const int wm = wid >> 1, wn = wid & 1;

    // decode upper-tri tile index t -> (a, b), a <= b
    const int t = blockIdx.x;
    int b = (int)((sqrtf(8.0f * (float)t + 1.0f) - 1.0f) * 0.5f);
    while (b * (b + 1) / 2 > t) --b;
    while ((b + 1) * (b + 2) / 2 <= t) ++b;
    const int a = t - b * (b + 1) / 2;
    const bool offdiag = (a != b);

    const int ibase = a * TM, jbase = b * TN;
    const int m0 = wm * 32, n0 = wn * 64;

    // j-block labels and first-pos into smem
    if (tid < TN) {
        int j = jbase + tid;
        int c = g_lab[j];
        ((int*)(sm + SM_LABS))[tid] = c;
        ((int*)(sm + SM_FP))[tid] = (j == g_first[c]) ? g_second[c] : g_first[c];
    }

    // loader mapping: each thread 16B, rows tid>>3 step 32, seg = tid&7
    const int lrow = tid >> 3, lseg = tid & 7;
    const char* gAb = (const char*)g_xq + (size_t)(ibase + lrow) * D + lseg * 16;
    const char* gBb = (const char*)g_xq + (size_t)(jbase + lrow) * D + lseg * 16;
    unsigned ldoff[4];
#pragma unroll
    for (int r = 0; r < 4; ++r) ldoff[r] = SWZ((lrow + r * 32) * 128 + lseg * 16);

#define LOAD_STAGE(c)                                                              \
    do {                                                                           \
        unsigned _st = tb + (unsigned)((c) % STAGES) * STAGE_BYTES;                \
        _Pragma("unroll")                                                          \
        for (int _r = 0; _r < 4; ++_r) {                                           \
            cpasync16(_st + ldoff[_r], gAb + (size_t)_r * 32 * D + (c) * 128);     \
            cpasync16(_st + B_OFF + ldoff[_r], gBb + (size_t)_r * 32 * D + (c) * 128); \
        }                                                                          \
    } while (0)

    LOAD_STAGE(0);
    asm volatile("cp.async.commit_group;" ::: "memory");
    LOAD_STAGE(1);
    asm volatile("cp.async.commit_group;" ::: "memory");

    float acc[2][8][4];
#pragma unroll
    for (int mi = 0; mi < 2; ++mi)
#pragma unroll
        for (int ni = 0; ni < 8; ++ni)
#pragma unroll
            for (int q = 0; q < 4; ++q) acc[mi][ni][q] = 0.0f;

    // precomputed ldsm row bases: addr = st + rowbase + (cb ^ sw)
    const int lm16 = lane & 15;
    const int khi = (lane >> 4) * 16;
    unsigned rbA0 = (unsigned)(m0 + lm16) * 128u;
    unsigned rbA1 = (unsigned)(m0 + 16 + lm16) * 128u;
    unsigned swA0 = (rbA0 >> 3) & 0x70u, swA1 = (rbA1 >> 3) & 0x70u;
    unsigned rbB[4], swB[4];
#pragma unroll
    for (int nt = 0; nt < 4; ++nt) {
        rbB[nt] = (unsigned)(n0 + nt * 16 + lm16) * 128u;
        swB[nt] = (rbB[nt] >> 3) & 0x70u;
    }

#pragma unroll 1
    for (int c = 0; c < NCHUNK; ++c) {
        if (c + 2 < NCHUNK) LOAD_STAGE(c + 2);
        asm volatile("cp.async.commit_group;" ::: "memory");
        asm volatile("cp.async.wait_group %0;" :: "n"(STAGES - 1) : "memory");
        __syncthreads();
        const unsigned st = tb + (unsigned)(c % STAGES) * STAGE_BYTES;
#pragma unroll
        for (int kk = 0; kk < 4; ++kk) {
            const unsigned cb = (unsigned)(kk * 32 + khi);
            unsigned a0[4], a1[4], bb[4][4];
            ldsm4(a0, st + rbA0 + (cb ^ swA0));
            ldsm4(a1, st + rbA1 + (cb ^ swA1));
#pragma unroll
            for (int nt = 0; nt < 4; ++nt)
                ldsm4(bb[nt], st + B_OFF + rbB[nt] + (cb ^ swB[nt]));
#pragma unroll
            for (int nt = 0; nt < 4; ++nt) {
                mma16832(acc[0][2 * nt + 0], a0, bb[nt][0], bb[nt][2]);
                mma16832(acc[0][2 * nt + 1], a0, bb[nt][1], bb[nt][3]);
                mma16832(acc[1][2 * nt + 0], a1, bb[nt][0], bb[nt][2]);
                mma16832(acc[1][2 * nt + 1], a1, bb[nt][1], bb[nt][3]);
            }
        }
        __syncthreads();
    }

    // ---- fused epilogue: row-sums (slot b) and, off-diagonal, col-sums (slot a) ----
    const int* labsB = (const int*)(sm + SM_LABS);
    const int* fpB = (const int*)(sm + SM_FP);

    int rowlab[4], rowfp[4];
#pragma unroll
    for (int mi = 0; mi < 2; ++mi)
#pragma unroll
        for (int h = 0; h < 2; ++h) {
            int grow = ibase + m0 + mi * 16 + h * 8 + (lane >> 2);
            int c = g_lab[grow];
            rowlab[mi * 2 + h] = c;
            rowfp[mi * 2 + h] = (grow == g_first[c]) ? g_second[c] : g_first[c];
        }

    float rs4[4] = {0.0f, 0.0f, 0.0f, 0.0f};
    float cs[8][2];
#pragma unroll
    for (int ni = 0; ni < 8; ++ni) { cs[ni][0] = 0.0f; cs[ni][1] = 0.0f; }

    const float SCL = 0.25f / 256.0f;  // acc = 256*cos -> S = 0.25*cos + 0.25
#pragma unroll
    for (int mi = 0; mi < 2; ++mi)
#pragma unroll
        for (int h = 0; h < 2; ++h) {
            const int ri = mi * 2 + h;
            const int rl = rowlab[ri], rf = rowfp[ri];
            const int grow = ibase + m0 + mi * 16 + h * 8 + (lane >> 2);
#pragma unroll
            for (int ni = 0; ni < 8; ++ni) {
                const int cl0 = n0 + ni * 8 + (lane & 3) * 2;
#pragma unroll
                for (int e = 0; e < 2; ++e) {
                    const int cl = cl0 + e;
                    float S = acc[mi][ni][h * 2 + e] * SCL + 0.25f;
                    float ex = __expf(S);
                    if (labsB[cl] != rl) { rs4[ri] += ex; cs[ni][e] += ex; }
                    if (jbase + cl == rf) g_posval[grow] = S;                 // unique writer
                    if (offdiag && fpB[cl] == grow) g_posval[jbase + cl] = S; // unique writer
                }
            }
        }

    // row reduce: lanes sharing lane>>2 hold the same rows
#pragma unroll
    for (int ri = 0; ri < 4; ++ri) {
        rs4[ri] += __shfl_xor_sync(0xffffffffu, rs4[ri], 1);
        rs4[ri] += __shfl_xor_sync(0xffffffffu, rs4[ri], 2);
    }
    float* rowred = (float*)(sm + SM_ROWRED);
    if ((lane & 3) == 0) {
#pragma unroll
        for (int mi = 0; mi < 2; ++mi)
#pragma unroll
            for (int h = 0; h < 2; ++h)
                rowred[wn * TM + m0 + mi * 16 + h * 8 + (lane >> 2)] = rs4[mi * 2 + h];
    }

    // col reduce: lanes sharing lane&3 hold the same cols
    if (offdiag) {
#pragma unroll
        for (int ni = 0; ni < 8; ++ni)
#pragma unroll
            for (int e = 0; e < 2; ++e) {
                cs[ni][e] += __shfl_xor_sync(0xffffffffu, cs[ni][e], 4);
                cs[ni][e] += __shfl_xor_sync(0xffffffffu, cs[ni][e], 8);
                cs[ni][e] += __shfl_xor_sync(0xffffffffu, cs[ni][e], 16);
            }
        float* colred = (float*)(sm + SM_COLRED);
        if (lane < 4) {
#pragma unroll
            for (int ni = 0; ni < 8; ++ni)
#pragma unroll
                for (int e = 0; e < 2; ++e)
                    colred[wm * TN + n0 + ni * 8 + lane * 2 + e] = cs[ni][e];
        }
    }
    __syncthreads();

    if (tid < TM)
        g_partial[b * N + ibase + tid] = rowred[tid] + rowred[TM + tid];
    if (offdiag && tid < TN) {
        const float* colred = (const float*)(sm + SM_COLRED);
        g_partial[a * N + jbase + tid] =
            colred[tid] + colred[TN + tid] + colred[2 * TN + tid] + colred[3 * TN + tid];
    }
}

// -------- kernel 5: combine partials, per-row loss, scalar mean --------
__global__ __launch_bounds__(1024) void k_final(float* __restrict__ out) {
    int t = threadIdx.x;
    float ls = 0.0f;
    for (int i = t; i < N; i += 1024) {
        float ns = 0.0f;
#pragma unroll
        for (int p = 0; p < NJT; ++p) ns += g_partial[p * N + i];
        float pv = g_posval[i];
        float Z = (float)(N - 2 + g_hist[g_lab[i]]);  // exp(0) structural zeros
        ls += __logf(__expf(pv) + ns + Z) - pv;
    }
#pragma unroll
    for (int o = 16; o; o >>= 1) ls += __shfl_down_sync(0xffffffffu, ls, o);
    __shared__ float ws[32];
    if ((t & 31) == 0) ws[t >> 5] = ls;
    __syncthreads();
    if (t == 0) {
        float tot = 0.0f;
#pragma unroll
        for (int j = 0; j < 32; ++j) tot += ws[j];
        out[0] = tot / (float)N;
    }
}

// -------- launch --------
extern "C" void kernel_launch(void* const* d_in, const int* in_sizes, int n_in,
                              void* d_out, int out_size) {
    const float* X = (const float*)d_in[0];
    const void* Y = d_in[1];
    float* out = (float*)d_out;

    static int smem_set = 0;
    if (!smem_set) {
        cudaFuncSetAttribute(k_gemm, cudaFuncAttributeMaxDynamicSharedMemorySize, SMEM_DYN);
        smem_set = 1;
    }

    k_init<<<1, 256>>>((const int*)Y);
    k_prep<<<N, 256>>>(X, Y);
    k_fp2<<<N / 256, 256>>>();
    k_gemm<<<NTILES, 256, SMEM_DYN>>>();
    k_final<<<1, 1024>>>(out);
}

// round 16
// speedup vs baseline: 1.0063x; 1.0013x over previous
#include <cuda_runtime.h>
#include <cuda_bf16.h>
#include <math.h>

#define N 4096
#define D 1024
#define NCLS 128
#define TM 128
#define TN 128
#define NCHUNK 8             // 8 chunks of 128 fp8 k-elements
#define NJT (N / TN)         // 32
#define NTILES (NJT * (NJT + 1) / 2)  // 528 upper-tri tiles
#define STAGES 3
#define STAGE_BYTES 32768    // A 16KB + B 16KB (128 rows x 128 B each)
#define B_OFF 16384

// dynamic smem layout
#define SM_LABS   64                    // int[128]
#define SM_FP     576                   // int[128]
#define SM_ROWRED 1088                  // float[2*128]
#define SM_COLRED 2112                  // float[4*128]
#define SM_TILES  4160
#define SMEM_DYN  (SM_TILES + 1024 + STAGES * STAGE_BYTES)  // 103488

// -------- device scratch --------
__device__ __align__(16) unsigned char g_xq[(size_t)N * D];  // e4m3(16 * xhat), 4 MB
__device__ int   g_lab[N];
__device__ int   g_first[NCLS];
__device__ int   g_second[NCLS];
__device__ int   g_hist[NCLS];
__device__ float g_posval[N];
__device__ float g_partial[NJT * N];
__device__ int   g_is64;

#define SWZ(x) ((unsigned)(x) ^ ((((unsigned)(x)) >> 3) & 0x70u))

__device__ __forceinline__ unsigned smem_u32(const void* p) {
    unsigned a;
    asm("{ .reg .u64 t; cvta.to.shared.u64 t, %1; cvt.u32.u64 %0, t; }" : "=r"(a) : "l"(p));
    return a;
}
__device__ __forceinline__ void ldsm4(unsigned r[4], unsigned addr) {
    asm volatile("ldmatrix.sync.aligned.m8n8.x4.shared.b16 {%0,%1,%2,%3}, [%4];"
                 : "=r"(r[0]), "=r"(r[1]), "=r"(r[2]), "=r"(r[3]) : "r"(addr));
}
// fp8 e4m3 MMA, k32: byte-layout of fragments identical to bf16 k16
__device__ __forceinline__ void mma16832(float d[4], const unsigned a[4], unsigned b0, unsigned b1) {
    asm volatile(
        "mma.sync.aligned.m16n8k32.row.col.f32.e4m3.e4m3.f32 "
        "{%0,%1,%2,%3}, {%4,%5,%6,%7}, {%8,%9}, {%0,%1,%2,%3};"
        : "+f"(d[0]), "+f"(d[1]), "+f"(d[2]), "+f"(d[3])
        : "r"(a[0]), "r"(a[1]), "r"(a[2]), "r"(a[3]), "r"(b0), "r"(b1));
}
__device__ __forceinline__ void cpasync16(unsigned dst, const void* src) {
    asm volatile("cp.async.cg.shared.global [%0], [%1], 16;" :: "r"(dst), "l"(src));
}

// -------- kernel 1: init + detect y_true width --------
__global__ void k_init(const int* __restrict__ Y32) {
    int t = threadIdx.x;
    int any = 0;
    for (int i = 2 * t + 1; i < N; i += 2 * blockDim.x) any |= Y32[i];
    int any_blk = __syncthreads_or(any);
    if (t == 0) g_is64 = (any_blk == 0) ? 1 : 0;
    if (t < NCLS) {
        g_hist[t] = 0;
        g_first[t] = 0x7fffffff;
        g_second[t] = 0x7fffffff;
    }
    for (int i = t; i < N; i += blockDim.x) g_posval[i] = 0.0f;
}

// -------- kernel 2: normalize rows -> fp8(16*xhat), labels, histogram, first[c] --------
__global__ __launch_bounds__(256) void k_prep(const float* __restrict__ X,
                                              const void* __restrict__ Yv) {
    int i = blockIdx.x;
    int t = threadIdx.x;
    float4 v = ((const float4*)(X + (size_t)i * D))[t];
    float s = v.x * v.x + v.y * v.y + v.z * v.z + v.w * v.w;
#pragma unroll
    for (int o = 16; o; o >>= 1) s += __shfl_down_sync(0xffffffffu, s, o);
    __shared__ float ws[8];
    if ((t & 31) == 0) ws[t >> 5] = s;
    __syncthreads();
    if (t == 0) {
        float tot = 0.0f;
#pragma unroll
        for (int j = 0; j < 8; ++j) tot += ws[j];
        ws[0] = 16.0f / fmaxf(sqrtf(tot), 1e-8f);   // scale by 16 for e4m3 range
        int lab = g_is64 ? (int)((const long long*)Yv)[i] : ((const int*)Yv)[i];
        lab = max(0, min(lab, NCLS - 1));
        g_lab[i] = lab;
        atomicAdd(&g_hist[lab], 1);
        atomicMin(&g_first[lab], i);
    }
    __syncthreads();
    float inv = ws[0];
    unsigned short r0, r1;
    asm("cvt.rn.satfinite.e4m3x2.f32 %0, %1, %2;" : "=h"(r0) : "f"(v.y * inv), "f"(v.x * inv));
    asm("cvt.rn.satfinite.e4m3x2.f32 %0, %1, %2;" : "=h"(r1) : "f"(v.w * inv), "f"(v.z * inv));
    *(unsigned*)&g_xq[(size_t)i * D + (size_t)t * 4] = (unsigned)r0 | ((unsigned)r1 << 16);
}

// -------- kernel 3: per-class second-occurrence (O(N)) --------
__global__ __launch_bounds__(256) void k_fp2() {
    int i = blockIdx.x * 256 + threadIdx.x;
    if (i < N) {
        int c = g_lab[i];
        if (i != g_first[c]) atomicMin(&g_second[c], i);
    }
}

// -------- kernel 4: symmetric fp8 mma.sync GEMM + fused row/col masked-exp epilogue --------
// 1D grid of 528 upper-tri tiles (a <= b); 256 threads = 8 warps 4(m) x 2(n), warp 32x64.
__global__ __launch_bounds__(256, 2) void k_gemm() {
    extern __shared__ __align__(16) char sm[];
    const unsigned sbase = smem_u32(sm);
    const unsigned tb = (sbase + SM_TILES + 1023u) & ~1023u;
    const int tid = threadIdx.x;
    const int wid = tid >> 5, lane = tid & 31;
    const int wm = wid >> 1, wn = wid & 1;

    // decode upper-tri tile index t -> (a, b), a <= b
    const int t = blockIdx.x;
    int b = (int)((sqrtf(8.0f * (float)t + 1.0f) - 1.0f) * 0.5f);
    while (b * (b + 1) / 2 > t) --b;
    while ((b + 1) * (b + 2) / 2 <= t) ++b;
    const int a = t - b * (b + 1) / 2;
    const bool offdiag = (a != b);

    const int ibase = a * TM, jbase = b * TN;
    const int m0 = wm * 32, n0 = wn * 64;

    // j-block labels and first-pos into smem
    if (tid < TN) {
        int j = jbase + tid;
        int c = g_lab[j];
        ((int*)(sm + SM_LABS))[tid] = c;
        ((int*)(sm + SM_FP))[tid] = (j == g_first[c]) ? g_second[c] : g_first[c];
    }

    // loader mapping: each thread 16B, rows tid>>3 step 32, seg = tid&7
    const int lrow = tid >> 3, lseg = tid & 7;
    const char* gAb = (const char*)g_xq + (size_t)(ibase + lrow) * D + lseg * 16;
    const char* gBb = (const char*)g_xq + (size_t)(jbase + lrow) * D + lseg * 16;
    unsigned ldoff[4];
#pragma unroll
    for (int r = 0; r < 4; ++r) ldoff[r] = SWZ((lrow + r * 32) * 128 + lseg * 16);

#define LOAD_STAGE(c)                                                              \
    do {                                                                           \
        unsigned _st = tb + (unsigned)((c) % STAGES) * STAGE_BYTES;                \
        _Pragma("unroll")                                                          \
        for (int _r = 0; _r < 4; ++_r) {                                           \
            cpasync16(_st + ldoff[_r], gAb + (size_t)_r * 32 * D + (c) * 128);     \
            cpasync16(_st + B_OFF + ldoff[_r], gBb + (size_t)_r * 32 * D + (c) * 128); \
        }                                                                          \
    } while (0)

    LOAD_STAGE(0);
    asm volatile("cp.async.commit_group;" ::: "memory");
    LOAD_STAGE(1);
    asm volatile("cp.async.commit_group;" ::: "memory");

    float acc[2][8][4];
#pragma unroll
    for (int mi = 0; mi < 2; ++mi)
#pragma unroll
        for (int ni = 0; ni < 8; ++ni)
#pragma unroll
            for (int q = 0; q < 4; ++q) acc[mi][ni][q] = 0.0f;

    // precomputed ldsm row bases: addr = st + rowbase + (cb ^ sw)
    const int lm16 = lane & 15;
    const int khi = (lane >> 4) * 16;
    unsigned rbA0 = (unsigned)(m0 + lm16) * 128u;
    unsigned rbA1 = (unsigned)(m0 + 16 + lm16) * 128u;
    unsigned swA0 = (rbA0 >> 3) & 0x70u, swA1 = (rbA1 >> 3) & 0x70u;
    unsigned rbB[4], swB[4];
#pragma unroll
    for (int nt = 0; nt < 4; ++nt) {
        rbB[nt] = (unsigned)(n0 + nt * 16 + lm16) * 128u;
        swB[nt] = (rbB[nt] >> 3) & 0x70u;
    }

#pragma unroll 1
    for (int c = 0; c < NCHUNK; ++c) {
        if (c + 2 < NCHUNK) LOAD_STAGE(c + 2);
        asm volatile("cp.async.commit_group;" ::: "memory");
        asm volatile("cp.async.wait_group %0;" :: "n"(STAGES - 1) : "memory");
        __syncthreads();
        const unsigned st = tb + (unsigned)(c % STAGES) * STAGE_BYTES;
#pragma unroll
        for (int kk = 0; kk < 4; ++kk) {
            const unsigned cb = (unsigned)(kk * 32 + khi);
            unsigned a0[4], a1[4], bb[4][4];
            ldsm4(a0, st + rbA0 + (cb ^ swA0));
            ldsm4(a1, st + rbA1 + (cb ^ swA1));
#pragma unroll
            for (int nt = 0; nt < 4; ++nt)
                ldsm4(bb[nt], st + B_OFF + rbB[nt] + (cb ^ swB[nt]));
#pragma unroll
            for (int nt = 0; nt < 4; ++nt) {
                mma16832(acc[0][2 * nt + 0], a0, bb[nt][0], bb[nt][2]);
                mma16832(acc[0][2 * nt + 1], a0, bb[nt][1], bb[nt][3]);
                mma16832(acc[1][2 * nt + 0], a1, bb[nt][0], bb[nt][2]);
                mma16832(acc[1][2 * nt + 1], a1, bb[nt][1], bb[nt][3]);
            }
        }
        __syncthreads();
    }

    // ---- fused epilogue: row-sums (slot b) and, off-diagonal, col-sums (slot a) ----
    const int* labsB = (const int*)(sm + SM_LABS);
    const int* fpB = (const int*)(sm + SM_FP);

    int rowlab[4], rowfp[4];
#pragma unroll
    for (int mi = 0; mi < 2; ++mi)
#pragma unroll
        for (int h = 0; h < 2; ++h) {
            int grow = ibase + m0 + mi * 16 + h * 8 + (lane >> 2);
            int c = g_lab[grow];
            rowlab[mi * 2 + h] = c;
            rowfp[mi * 2 + h] = (grow == g_first[c]) ? g_second[c] : g_first[c];
        }

    float rs4[4] = {0.0f, 0.0f, 0.0f, 0.0f};
    float cs[8][2];
#pragma unroll
    for (int ni = 0; ni < 8; ++ni) { cs[ni][0] = 0.0f; cs[ni][1] = 0.0f; }

    const float SCL = 0.25f / 256.0f;  // acc = 256*cos -> S = 0.25*cos + 0.25
#pragma unroll
    for (int mi = 0; mi < 2; ++mi)
#pragma unroll
        for (int h = 0; h < 2; ++h) {
            const int ri = mi * 2 + h;
            const int rl = rowlab[ri], rf = rowfp[ri];
            const int grow = ibase + m0 + mi * 16 + h * 8 + (lane >> 2);
#pragma unroll
            for (int ni = 0; ni < 8; ++ni) {
                const int cl0 = n0 + ni * 8 + (lane & 3) * 2;
#pragma unroll
                for (int e = 0; e < 2; ++e) {
                    const int cl = cl0 + e;
                    float S = acc[mi][ni][h * 2 + e] * SCL + 0.25f;
                    float ex = __expf(S);
                    if (labsB[cl] != rl) { rs4[ri] += ex; cs[ni][e] += ex; }
                    if (jbase + cl == rf) g_posval[grow] = S;                 // unique writer
                    if (offdiag && fpB[cl] == grow) g_posval[jbase + cl] = S; // unique writer
                }
            }
        }

    // row reduce: lanes sharing lane>>2 hold the same rows
#pragma unroll
    for (int ri = 0; ri < 4; ++ri) {
        rs4[ri] += __shfl_xor_sync(0xffffffffu, rs4[ri], 1);
        rs4[ri] += __shfl_xor_sync(0xffffffffu, rs4[ri], 2);
    }
    float* rowred = (float*)(sm + SM_ROWRED);
    if ((lane & 3) == 0) {
#pragma unroll
        for (int mi = 0; mi < 2; ++mi)
#pragma unroll
            for (int h = 0; h < 2; ++h)
                rowred[wn * TM + m0 + mi * 16 + h * 8 + (lane >> 2)] = rs4[mi * 2 + h];
    }

    // col reduce: lanes sharing lane&3 hold the same cols
    if (offdiag) {
#pragma unroll
        for (int ni = 0; ni < 8; ++ni)
#pragma unroll
            for (int e = 0; e < 2; ++e) {
                cs[ni][e] += __shfl_xor_sync(0xffffffffu, cs[ni][e], 4);
                cs[ni][e] += __shfl_xor_sync(0xffffffffu, cs[ni][e], 8);
                cs[ni][e] += __shfl_xor_sync(0xffffffffu, cs[ni][e], 16);
            }
        float* colred = (float*)(sm + SM_COLRED);
        if (lane < 4) {
#pragma unroll
            for (int ni = 0; ni < 8; ++ni)
#pragma unroll
                for (int e = 0; e < 2; ++e)
                    colred[wm * TN + n0 + ni * 8 + lane * 2 + e] = cs[ni][e];
        }
    }
    __syncthreads();

    if (tid < TM)
        g_partial[b * N + ibase + tid] = rowred[tid] + rowred[TM + tid];
    if (offdiag && tid < TN) {
        const float* colred = (const float*)(sm + SM_COLRED);
        g_partial[a * N + jbase + tid] =
            colred[tid] + colred[TN + tid] + colred[2 * TN + tid] + colred[3 * TN + tid];
    }
}

// -------- kernel 5: combine partials, per-row loss, scalar mean --------
__global__ __launch_bounds__(1024) void k_final(float* __restrict__ out) {
    int t = threadIdx.x;
    float ls = 0.0f;
    for (int i = t; i < N; i += 1024) {
        float ns = 0.0f;
#pragma unroll
        for (int p = 0; p < NJT; ++p) ns += g_partial[p * N + i];
        float pv = g_posval[i];
        float Z = (float)(N - 2 + g_hist[g_lab[i]]);  // exp(0) structural zeros
        ls += __logf(__expf(pv) + ns + Z) - pv;
    }
#pragma unroll
    for (int o = 16; o; o >>= 1) ls += __shfl_down_sync(0xffffffffu, ls, o);
    __shared__ float ws[32];
    if ((t & 31) == 0) ws[t >> 5] = ls;
    __syncthreads();
    if (t == 0) {
        float tot = 0.0f;
#pragma unroll
        for (int j = 0; j < 32; ++j) tot += ws[j];
        out[0] = tot / (float)N;
    }
}

// -------- launch --------
extern "C" void kernel_launch(void* const* d_in, const int* in_sizes, int n_in,
                              void* d_out, int out_size) {
    const float* X = (const float*)d_in[0];
    const void* Y = d_in[1];
    float* out = (float*)d_out;

    static int smem_set = 0;
    if (!smem_set) {
        cudaFuncSetAttribute(k_gemm, cudaFuncAttributeMaxDynamicSharedMemorySize, SMEM_DYN);
        smem_set = 1;
    }

    k_init<<<1, 256>>>((const int*)Y);
    k_prep<<<N, 256>>>(X, Y);
    k_fp2<<<N / 256, 256>>>();
    k_gemm<<<NTILES, 256, SMEM_DYN>>>();
    k_final<<<1, 1024>>>(out);
}